// round 9
// baseline (speedup 1.0000x reference)
#include <cuda_runtime.h>
#include <cuda_fp16.h>
#include <cstdint>

// ---------------- problem constants ----------------
#define CIN   256
#define KOUT  256
#define HH    56
#define WW    56
#define NPF   2304           // 256*3*3 per output filter
#define PH    58
#define PW    58
#define NIMG  32
#define PIX   (HH*WW)        // 3136
#define MTOT  (NIMG*PIX)     // 100352

// ---------------- GEMM tiling ----------------
#define MT    128            // CTA M tile
#define NT    256            // CTA N tile (all output channels)
#define KC    32             // K chunk (halfs)
#define NCH   72             // 9 taps * 8 chunks of 32 channels
#define NS    4              // pipeline stages

// smem stage: A(128 rows x 80B) + B(256 rows x 80B); 80B stride -> conflict-free ldsm
#define ROWB  80
#define ASTG  (128*ROWB)     // 10240
#define BSTG  (256*ROWB)     // 20480
#define STG   (ASTG+BSTG)    // 30720
#define SMDYN (NS*STG)       // 122880

// ---------------- device scratch ----------------
__device__ __half g_b[9 * KOUT * CIN];                   // [rs][k][c], +-1
__device__ float  g_alpha[KOUT];
__device__ __half g_xpad[(size_t)NIMG * PH * PW * CIN];  // [n][hp][wp][c]

// ---------------- ptx helpers (family-portable only) ----------------
__device__ __forceinline__ void cp16(uint32_t dst, const void* src) {
    asm volatile("cp.async.cg.shared.global [%0], [%1], 16;"
                 :: "r"(dst), "l"(__cvta_generic_to_global(src)) : "memory");
}
#define CP_COMMIT()  asm volatile("cp.async.commit_group;" ::: "memory")
#define CP_WAIT(N)   asm volatile("cp.async.wait_group %0;" :: "n"(N) : "memory")

#define LDSM4(R, addr)                                                        \
    asm volatile("ldmatrix.sync.aligned.m8n8.x4.shared.b16 {%0,%1,%2,%3}, [%4];" \
                 : "=r"((R)[0]), "=r"((R)[1]), "=r"((R)[2]), "=r"((R)[3])     \
                 : "r"(addr))

#define MMA16816(D, A, B0, B1)                                                \
    asm volatile("mma.sync.aligned.m16n8k16.row.col.f32.f16.f16.f32 "         \
                 "{%0,%1,%2,%3}, {%4,%5,%6,%7}, {%8,%9}, {%0,%1,%2,%3};"      \
                 : "+f"((D)[0]), "+f"((D)[1]), "+f"((D)[2]), "+f"((D)[3])     \
                 : "r"((A)[0]), "r"((A)[1]), "r"((A)[2]), "r"((A)[3]),        \
                   "r"(B0), "r"(B1))

// ---------------------------------------------------------------------------
// K0: ternarize (float4 + warp shuffle reductions). One block per filter.
// ---------------------------------------------------------------------------
__global__ void ternarize_kernel(const float* __restrict__ w) {
    const int o = blockIdx.x;
    const int tid = threadIdx.x;
    const int lane = tid & 31;
    const int wrp = tid >> 5;
    const float4* wo4 = (const float4*)(w + (size_t)o * NPF);
    __shared__ float red[8];
    __shared__ float s_delta;

    float s = 0.f;
    for (int i = tid; i < NPF / 4; i += 256) {
        float4 v = wo4[i];
        s += fabsf(v.x) + fabsf(v.y) + fabsf(v.z) + fabsf(v.w);
    }
    #pragma unroll
    for (int d = 16; d > 0; d >>= 1) s += __shfl_xor_sync(~0u, s, d);
    if (lane == 0) red[wrp] = s;
    __syncthreads();
    if (tid == 0) {
        float t = 0.f;
        #pragma unroll
        for (int i = 0; i < 8; i++) t += red[i];
        s_delta = (0.7f / (float)NPF) * t;
    }
    __syncthreads();
    const float delta = s_delta;

    float cnt = 0.f, asum = 0.f;
    for (int i = tid; i < NPF / 4; i += 256) {
        float4 v = wo4[i];
        float a;
        a = fabsf(v.x); if (a > delta) { cnt += 1.f; asum += a; }
        a = fabsf(v.y); if (a > delta) { cnt += 1.f; asum += a; }
        a = fabsf(v.z); if (a > delta) { cnt += 1.f; asum += a; }
        a = fabsf(v.w); if (a > delta) { cnt += 1.f; asum += a; }
    }
    #pragma unroll
    for (int d = 16; d > 0; d >>= 1) {
        cnt  += __shfl_xor_sync(~0u, cnt, d);
        asum += __shfl_xor_sync(~0u, asum, d);
    }
    if (lane == 0) red[wrp] = cnt;
    __syncthreads();
    float cnt_tot = 0.f;
    if (tid == 0) {
        #pragma unroll
        for (int i = 0; i < 8; i++) cnt_tot += red[i];
        red[0] = cnt_tot;
    }
    __syncthreads();
    cnt_tot = red[0];
    __syncthreads();
    if (lane == 0) red[wrp] = asum;
    __syncthreads();
    if (tid == 0) {
        float t = 0.f;
        #pragma unroll
        for (int i = 0; i < 8; i++) t += red[i];
        g_alpha[o] = t / cnt_tot;
    }

    const float* wo = w + (size_t)o * NPF;
    for (int i = tid; i < NPF; i += 256) {
        float v = wo[i];
        float t = (v > delta) ? 1.f : ((v < -delta) ? -1.f : 0.f);
        int c = i / 9, rs = i % 9;
        g_b[((size_t)rs * KOUT + o) * CIN + c] = __float2half_rn(t);
    }
}

// ---------------------------------------------------------------------------
// K1: pad + NCHW->NHWC transpose + fp16 convert (border rows write zeros).
// ---------------------------------------------------------------------------
__global__ void pad_transpose_kernel(const float* __restrict__ x) {
    __shared__ float s[64][57];
    const int hp = blockIdx.x, c0 = blockIdx.y * 64, n = blockIdx.z;
    __half* dst = g_xpad + ((size_t)(n * PH + hp) * PW) * CIN + c0;

    if (hp == 0 || hp == PH - 1) {
        for (int idx = threadIdx.x; idx < PW * 8; idx += 256) {
            int wp = idx >> 3, u = idx & 7;
            ((uint4*)(dst + (size_t)wp * CIN))[u] = make_uint4(0u, 0u, 0u, 0u);
        }
        return;
    }

    const int h = hp - 1;
    const float* xp = x + ((size_t)(n * CIN + c0) * HH + h) * WW;
    for (int idx = threadIdx.x; idx < 64 * WW; idx += 256) {
        int ci = idx / WW, w = idx - ci * WW;
        s[ci][w] = xp[(size_t)ci * PIX + w];
    }
    __syncthreads();

    for (int idx = threadIdx.x; idx < PW * 64; idx += 256) {
        int wp = idx / 64, ci = idx - wp * 64;
        float v = (wp >= 1 && wp <= WW) ? s[ci][wp - 1] : 0.f;
        dst[(size_t)wp * CIN + ci] = __float2half_rn(v);
    }
}

// ---------------------------------------------------------------------------
// K2: implicit-GEMM conv via mma.sync m16n8k16 (fp32 acc).
// Grid 784: CTA = 128 pixels x 256 out channels. 8 warps, warp tile 64x64
// (warp_m 0..1 x warp_n 0..3). NS=4 pipeline, prefetch distance 3.
// ---------------------------------------------------------------------------
__global__ void __launch_bounds__(256, 1)
conv_mma_kernel(const float* __restrict__ bias_g, float* __restrict__ out) {
    extern __shared__ __align__(128) char smem[];
    const uint32_t sb = (uint32_t)__cvta_generic_to_shared(smem);

    const int tid = threadIdx.x;
    const int lane = tid & 31;
    const int warp_m = (tid >> 5) >> 2;   // 0..1
    const int warp_n = (tid >> 5) & 3;    // 0..3

    const int p0 = blockIdx.x * MT;

    __shared__ float s_alpha[256], s_bias[256];
    s_alpha[tid] = g_alpha[tid];
    s_bias[tid]  = bias_g[tid];

    // ---- per-thread cp.async source/dest precompute ----
    const int seg = tid & 3;               // 16B segment of 64B row
    const int arow = tid >> 2;             // 0..63
    const __half* a_g[2];
    #pragma unroll
    for (int q = 0; q < 2; q++) {
        int row = arow + q * 64;
        int p = p0 + row;
        int n = p / PIX; int rem = p - n * PIX;
        int h = rem / WW; int w = rem - h * WW;
        a_g[q] = g_xpad + ((size_t)((n * PH + h) * PW + w)) * CIN + seg * 8;
    }
    const __half* b_g[4];
    #pragma unroll
    for (int q = 0; q < 4; q++)
        b_g[q] = g_b + (size_t)(arow + q * 64) * CIN + seg * 8;
    const uint32_t sa_off = (uint32_t)(arow * ROWB + seg * 16);
    uint32_t sb_off[4];
    #pragma unroll
    for (int q = 0; q < 4; q++)
        sb_off[q] = (uint32_t)((arow + q * 64) * ROWB + seg * 16);

    // ---- ldmatrix address precompute ----
    uint32_t a_lm[4];
    {
        int rr = lane & 15;
        int ch = (lane >> 4) * 8;
        #pragma unroll
        for (int i = 0; i < 4; i++)
            a_lm[i] = (uint32_t)((warp_m * 64 + i * 16 + rr) * ROWB + ch * 2);
    }
    uint32_t b_lm[4];
    {
        int nn = (lane & 7) + ((lane & 16) >> 1);
        int kk0 = lane & 8;
        #pragma unroll
        for (int j = 0; j < 4; j++)
            b_lm[j] = (uint32_t)((warp_n * 64 + j * 16 + nn) * ROWB + kk0 * 2);
    }

    float acc[4][8][4];
    #pragma unroll
    for (int i = 0; i < 4; i++)
        #pragma unroll
        for (int j = 0; j < 8; j++)
            #pragma unroll
            for (int r = 0; r < 4; r++) acc[i][j][r] = 0.f;

    auto fill = [&](int st, int ch) {
        int rs = ch >> 3, cc = ch & 7;
        int r = rs / 3, s = rs - r * 3;
        size_t aoff = (size_t)((r * PW + s) * CIN + cc * KC);
        size_t boff = (size_t)rs * (KOUT * CIN) + cc * KC;
        uint32_t ab = sb + st * STG;
        uint32_t bb = ab + ASTG;
        cp16(ab + sa_off, a_g[0] + aoff);
        cp16(ab + sa_off + 64 * ROWB, a_g[1] + aoff);
        #pragma unroll
        for (int q = 0; q < 4; q++) cp16(bb + sb_off[q], b_g[q] + boff);
        CP_COMMIT();
    };

    // ---- pipelined mainloop: 3 stages in flight ----
    fill(0, 0); fill(1, 1); fill(2, 2);

    int st = 0;
    for (int ch = 0; ch < NCH; ch++) {
        CP_WAIT(2);
        __syncthreads();
        if (ch + 3 < NCH) fill((st + 3) & (NS - 1), ch + 3);
        else              CP_COMMIT();

        uint32_t ab = sb + st * STG;
        uint32_t bb = ab + ASTG;
        #pragma unroll
        for (int kk = 0; kk < 2; kk++) {
            uint32_t a[4][4], b[4][4];
            #pragma unroll
            for (int i = 0; i < 4; i++) LDSM4(a[i], ab + a_lm[i] + kk * 32);
            #pragma unroll
            for (int j = 0; j < 4; j++) LDSM4(b[j], bb + b_lm[j] + kk * 32);
            #pragma unroll
            for (int i = 0; i < 4; i++)
                #pragma unroll
                for (int j = 0; j < 8; j++)
                    MMA16816(acc[i][j], a[i],
                             b[j >> 1][(j & 1) * 2],
                             b[j >> 1][(j & 1) * 2 + 1]);
        }
        st = (st + 1) & (NS - 1);
    }
    CP_WAIT(0);
    __syncthreads();

    // ---- epilogue: 4 phases of 64 channels, staged through smem ----
    float* stile = (float*)smem;   // [128][65] = 33.3KB
    const int m_ep = tid & 127;
    const int kb = tid >> 7;       // 0/1
    int p = p0 + m_ep;
    int nimg = p / PIX; int hw = p - nimg * PIX;

    #pragma unroll
    for (int phase = 0; phase < 4; phase++) {
        #pragma unroll
        for (int i = 0; i < 4; i++)
            #pragma unroll
            for (int j = 0; j < 8; j++) {
                int nl = warp_n * 64 + j * 8 + (lane & 3) * 2;
                if ((nl >> 6) == phase) {
                    int no = nl & 63;
                    int m0 = warp_m * 64 + i * 16 + (lane >> 2);
                    stile[m0 * 65 + no]           = acc[i][j][0];
                    stile[m0 * 65 + no + 1]       = acc[i][j][1];
                    stile[(m0 + 8) * 65 + no]     = acc[i][j][2];
                    stile[(m0 + 8) * 65 + no + 1] = acc[i][j][3];
                }
            }
        __syncthreads();

        float* ob = out + ((size_t)nimg * KOUT + phase * 64) * PIX + hw;
        #pragma unroll
        for (int it = 0; it < 32; it++) {
            int k = it * 2 + kb;
            int kg = phase * 64 + k;
            float v = stile[m_ep * 65 + k];
            ob[(size_t)k * PIX] = fmaf(s_alpha[kg], v, s_bias[kg]);
        }
        __syncthreads();
    }
}

// ---------------------------------------------------------------------------
extern "C" void kernel_launch(void* const* d_in, const int* in_sizes, int n_in,
                              void* d_out, int out_size) {
    const float* x      = (const float*)d_in[0];
    const float* weight = (const float*)d_in[1];
    const float* bias   = (const float*)d_in[2];
    float* out          = (float*)d_out;

    cudaFuncSetAttribute(conv_mma_kernel,
                         cudaFuncAttributeMaxDynamicSharedMemorySize, SMDYN);

    ternarize_kernel<<<KOUT, 256>>>(weight);
    pad_transpose_kernel<<<dim3(PH, 4, NIMG), 256>>>(x);
    conv_mma_kernel<<<MTOT / MT, 256, SMDYN>>>(bias, out);
}

// round 10
// speedup vs baseline: 1.1771x; 1.1771x over previous
#include <cuda_runtime.h>
#include <cuda_fp16.h>
#include <cstdint>

// ---------------- problem constants ----------------
#define CIN   256
#define KOUT  256
#define HH    56
#define WW    56
#define NPF   2304           // 256*3*3 per output filter
#define PH    58
#define PW    58
#define NIMG  32
#define PIX   (HH*WW)        // 3136
#define MTOT  (NIMG*PIX)     // 100352

// ---------------- GEMM tiling ----------------
#define MT    128            // CTA M tile
#define NT    128            // CTA N tile
#define KC    32             // K chunk (halfs)
#define NCH   72             // 9 taps * 8 chunks of 32 channels
#define NS    4              // pipeline stages

// smem stage: A(128 rows x 80B) + B(128 rows x 80B); 80B stride -> conflict-free ldsm
#define ROWB  80
#define ASTG  (128*ROWB)     // 10240
#define STG   (2*ASTG)       // 20480
#define SMDYN (NS*STG)       // 81920

// ---------------- device scratch ----------------
__device__ __half g_b[9 * KOUT * CIN];                   // [rs][k][c], +-1
__device__ float  g_alpha[KOUT];
__device__ __half g_xpad[(size_t)NIMG * PH * PW * CIN];  // [n][hp][wp][c]

// ---------------- ptx helpers (family-portable only) ----------------
__device__ __forceinline__ void cp16(uint32_t dst, const void* src) {
    asm volatile("cp.async.cg.shared.global [%0], [%1], 16;"
                 :: "r"(dst), "l"(__cvta_generic_to_global(src)) : "memory");
}
#define CP_COMMIT()  asm volatile("cp.async.commit_group;" ::: "memory")
#define CP_WAIT(N)   asm volatile("cp.async.wait_group %0;" :: "n"(N) : "memory")

#define LDSM4(R, addr)                                                        \
    asm volatile("ldmatrix.sync.aligned.m8n8.x4.shared.b16 {%0,%1,%2,%3}, [%4];" \
                 : "=r"((R)[0]), "=r"((R)[1]), "=r"((R)[2]), "=r"((R)[3])     \
                 : "r"(addr))

#define MMA16816(D, A, B0, B1)                                                \
    asm volatile("mma.sync.aligned.m16n8k16.row.col.f32.f16.f16.f32 "         \
                 "{%0,%1,%2,%3}, {%4,%5,%6,%7}, {%8,%9}, {%0,%1,%2,%3};"      \
                 : "+f"((D)[0]), "+f"((D)[1]), "+f"((D)[2]), "+f"((D)[3])     \
                 : "r"((A)[0]), "r"((A)[1]), "r"((A)[2]), "r"((A)[3]),        \
                   "r"(B0), "r"(B1))

// ---------------------------------------------------------------------------
// K0: ternarize (float4 + warp shuffle reductions). One block per filter.
// ---------------------------------------------------------------------------
__global__ void ternarize_kernel(const float* __restrict__ w) {
    const int o = blockIdx.x;
    const int tid = threadIdx.x;
    const int lane = tid & 31;
    const int wrp = tid >> 5;
    const float4* wo4 = (const float4*)(w + (size_t)o * NPF);
    __shared__ float red[8];
    __shared__ float s_delta;

    float s = 0.f;
    for (int i = tid; i < NPF / 4; i += 256) {
        float4 v = wo4[i];
        s += fabsf(v.x) + fabsf(v.y) + fabsf(v.z) + fabsf(v.w);
    }
    #pragma unroll
    for (int d = 16; d > 0; d >>= 1) s += __shfl_xor_sync(~0u, s, d);
    if (lane == 0) red[wrp] = s;
    __syncthreads();
    if (tid == 0) {
        float t = 0.f;
        #pragma unroll
        for (int i = 0; i < 8; i++) t += red[i];
        s_delta = (0.7f / (float)NPF) * t;
    }
    __syncthreads();
    const float delta = s_delta;

    float cnt = 0.f, asum = 0.f;
    for (int i = tid; i < NPF / 4; i += 256) {
        float4 v = wo4[i];
        float a;
        a = fabsf(v.x); if (a > delta) { cnt += 1.f; asum += a; }
        a = fabsf(v.y); if (a > delta) { cnt += 1.f; asum += a; }
        a = fabsf(v.z); if (a > delta) { cnt += 1.f; asum += a; }
        a = fabsf(v.w); if (a > delta) { cnt += 1.f; asum += a; }
    }
    #pragma unroll
    for (int d = 16; d > 0; d >>= 1) {
        cnt  += __shfl_xor_sync(~0u, cnt, d);
        asum += __shfl_xor_sync(~0u, asum, d);
    }
    if (lane == 0) red[wrp] = cnt;
    __syncthreads();
    float cnt_tot = 0.f;
    if (tid == 0) {
        #pragma unroll
        for (int i = 0; i < 8; i++) cnt_tot += red[i];
        red[0] = cnt_tot;
    }
    __syncthreads();
    cnt_tot = red[0];
    __syncthreads();
    if (lane == 0) red[wrp] = asum;
    __syncthreads();
    if (tid == 0) {
        float t = 0.f;
        #pragma unroll
        for (int i = 0; i < 8; i++) t += red[i];
        g_alpha[o] = t / cnt_tot;
    }

    const float* wo = w + (size_t)o * NPF;
    for (int i = tid; i < NPF; i += 256) {
        float v = wo[i];
        float t = (v > delta) ? 1.f : ((v < -delta) ? -1.f : 0.f);
        int c = i / 9, rs = i % 9;
        g_b[((size_t)rs * KOUT + o) * CIN + c] = __float2half_rn(t);
    }
}

// ---------------------------------------------------------------------------
// K1: pad + NCHW->NHWC transpose + fp16 convert (border rows write zeros).
// ---------------------------------------------------------------------------
__global__ void pad_transpose_kernel(const float* __restrict__ x) {
    __shared__ float s[64][57];
    const int hp = blockIdx.x, c0 = blockIdx.y * 64, n = blockIdx.z;
    __half* dst = g_xpad + ((size_t)(n * PH + hp) * PW) * CIN + c0;

    if (hp == 0 || hp == PH - 1) {
        for (int idx = threadIdx.x; idx < PW * 8; idx += 256) {
            int wp = idx >> 3, u = idx & 7;
            ((uint4*)(dst + (size_t)wp * CIN))[u] = make_uint4(0u, 0u, 0u, 0u);
        }
        return;
    }

    const int h = hp - 1;
    const float* xp = x + ((size_t)(n * CIN + c0) * HH + h) * WW;
    for (int idx = threadIdx.x; idx < 64 * WW; idx += 256) {
        int ci = idx / WW, w = idx - ci * WW;
        s[ci][w] = xp[(size_t)ci * PIX + w];
    }
    __syncthreads();

    for (int idx = threadIdx.x; idx < PW * 64; idx += 256) {
        int wp = idx / 64, ci = idx - wp * 64;
        float v = (wp >= 1 && wp <= WW) ? s[ci][wp - 1] : 0.f;
        dst[(size_t)wp * CIN + ci] = __float2half_rn(v);
    }
}

// ---------------------------------------------------------------------------
// K2: implicit-GEMM conv via mma.sync m16n8k16 (fp32 acc).
// Grid (784, 2): CTA = 128 pixels x 128 out channels. 8 warps, warp 64x32,
// 2 CTAs/SM. Chunks processed in PAIRS: one CP_WAIT + one __syncthreads per
// 2 chunks; next-pair fills issued right after the sync so cp.async overlaps
// the entire pair's compute (de-convoys the barrier phase-lock).
// ---------------------------------------------------------------------------
__global__ void __launch_bounds__(256, 2)
conv_mma_kernel(const float* __restrict__ bias_g, float* __restrict__ out) {
    extern __shared__ __align__(128) char smem[];
    const uint32_t sb = (uint32_t)__cvta_generic_to_shared(smem);

    const int tid = threadIdx.x;
    const int lane = tid & 31;
    const int warp_m = (tid >> 5) >> 2;   // 0..1
    const int warp_n = (tid >> 5) & 3;    // 0..3

    const int p0 = blockIdx.x * MT;
    const int n0 = blockIdx.y * NT;

    __shared__ float s_alpha[128], s_bias[128];
    if (tid < 128) s_alpha[tid] = g_alpha[n0 + tid];
    else           s_bias[tid - 128] = bias_g[n0 + tid - 128];

    // ---- per-thread cp.async source/dest precompute ----
    const int seg = tid & 3;               // 16B segment of 64B row
    const int arow = tid >> 2;             // 0..63
    const __half* a_g[2];
    #pragma unroll
    for (int q = 0; q < 2; q++) {
        int row = arow + q * 64;
        int p = p0 + row;
        int n = p / PIX; int rem = p - n * PIX;
        int h = rem / WW; int w = rem - h * WW;
        a_g[q] = g_xpad + ((size_t)((n * PH + h) * PW + w)) * CIN + seg * 8;
    }
    const __half* b_g[2];
    #pragma unroll
    for (int q = 0; q < 2; q++)
        b_g[q] = g_b + (size_t)(n0 + arow + q * 64) * CIN + seg * 8;
    const uint32_t s_off0 = (uint32_t)(arow * ROWB + seg * 16);
    const uint32_t s_off1 = s_off0 + 64 * ROWB;

    // ---- ldmatrix address precompute ----
    uint32_t a_lm[4];
    {
        int rr = lane & 15;
        int ch = (lane >> 4) * 8;
        #pragma unroll
        for (int i = 0; i < 4; i++)
            a_lm[i] = (uint32_t)((warp_m * 64 + i * 16 + rr) * ROWB + ch * 2);
    }
    uint32_t b_lm[2];
    {
        int nn = (lane & 7) + ((lane & 16) >> 1);
        int kk0 = lane & 8;
        #pragma unroll
        for (int j = 0; j < 2; j++)
            b_lm[j] = (uint32_t)((warp_n * 32 + j * 16 + nn) * ROWB + kk0 * 2);
    }

    float acc[4][4][4];
    #pragma unroll
    for (int i = 0; i < 4; i++)
        #pragma unroll
        for (int j = 0; j < 4; j++)
            #pragma unroll
            for (int r = 0; r < 4; r++) acc[i][j][r] = 0.f;

    auto fill = [&](int st, int ch) {
        int rs = ch >> 3, cc = ch & 7;
        int r = rs / 3, s = rs - r * 3;
        size_t aoff = (size_t)((r * PW + s) * CIN + cc * KC);
        size_t boff = (size_t)rs * (KOUT * CIN) + cc * KC;
        uint32_t ab = sb + st * STG;
        uint32_t bb = ab + ASTG;
        cp16(ab + s_off0, a_g[0] + aoff);
        cp16(ab + s_off1, a_g[1] + aoff);
        cp16(bb + s_off0, b_g[0] + boff);
        cp16(bb + s_off1, b_g[1] + boff);
        CP_COMMIT();
    };

    auto compute = [&](int st) {
        uint32_t ab = sb + st * STG;
        uint32_t bb = ab + ASTG;
        #pragma unroll
        for (int kk = 0; kk < 2; kk++) {
            uint32_t a[4][4], b[2][4];
            #pragma unroll
            for (int i = 0; i < 4; i++) LDSM4(a[i], ab + a_lm[i] + kk * 32);
            #pragma unroll
            for (int j = 0; j < 2; j++) LDSM4(b[j], bb + b_lm[j] + kk * 32);
            #pragma unroll
            for (int i = 0; i < 4; i++)
                #pragma unroll
                for (int j2 = 0; j2 < 4; j2++)
                    MMA16816(acc[i][j2], a[i],
                             b[j2 >> 1][(j2 & 1) * 2],
                             b[j2 >> 1][(j2 & 1) * 2 + 1]);
        }
    };

    // ---- paired-chunk pipelined mainloop ----
    // Invariant at pair start: outstanding cp.async groups = {ch, ch+1}.
    fill(0, 0); fill(1, 1);

    int st = 0;
    #pragma unroll 1
    for (int ch = 0; ch < NCH; ch += 2) {
        CP_WAIT(0);        // drain this pair's two fills (others' via barrier)
        __syncthreads();   // smem visibility + stage-reuse guard for fills below

        // prefetch next pair into stages st+2, st+3 (read last in PREVIOUS pair)
        if (ch + 2 < NCH) {
            fill((st + 2) & (NS - 1), ch + 2);
            fill((st + 3) & (NS - 1), ch + 3);
        }

        compute(st);
        compute((st + 1) & (NS - 1));
        st = (st + 2) & (NS - 1);
    }
    __syncthreads();

    // ---- epilogue: stage through smem, out = alpha*acc + bias ----
    float* stile = (float*)smem;   // [128][65]
    const int m_ep = tid & 127;
    const int kb = tid >> 7;       // 0/1
    int p = p0 + m_ep;
    int nimg = p / PIX; int hw = p - nimg * PIX;

    #pragma unroll
    for (int phase = 0; phase < 2; phase++) {
        #pragma unroll
        for (int i = 0; i < 4; i++)
            #pragma unroll
            for (int j2 = 0; j2 < 4; j2++) {
                int nl = warp_n * 32 + j2 * 8 + (lane & 3) * 2;
                if ((nl >> 6) == phase) {
                    int no = nl & 63;
                    int m0 = warp_m * 64 + i * 16 + (lane >> 2);
                    stile[m0 * 65 + no]           = acc[i][j2][0];
                    stile[m0 * 65 + no + 1]       = acc[i][j2][1];
                    stile[(m0 + 8) * 65 + no]     = acc[i][j2][2];
                    stile[(m0 + 8) * 65 + no + 1] = acc[i][j2][3];
                }
            }
        __syncthreads();

        float* ob = out + ((size_t)nimg * KOUT + n0 + phase * 64) * PIX + hw;
        #pragma unroll
        for (int it = 0; it < 32; it++) {
            int k = it * 2 + kb;
            int kg = phase * 64 + k;
            float v = stile[m_ep * 65 + k];
            ob[(size_t)k * PIX] = fmaf(s_alpha[kg], v, s_bias[kg]);
        }
        __syncthreads();
    }
}

// ---------------------------------------------------------------------------
extern "C" void kernel_launch(void* const* d_in, const int* in_sizes, int n_in,
                              void* d_out, int out_size) {
    const float* x      = (const float*)d_in[0];
    const float* weight = (const float*)d_in[1];
    const float* bias   = (const float*)d_in[2];
    float* out          = (float*)d_out;

    cudaFuncSetAttribute(conv_mma_kernel,
                         cudaFuncAttributeMaxDynamicSharedMemorySize, SMDYN);

    ternarize_kernel<<<KOUT, 256>>>(weight);
    pad_transpose_kernel<<<dim3(PH, 4, NIMG), 256>>>(x);
    conv_mma_kernel<<<dim3(MTOT / MT, KOUT / NT), 256, SMDYN>>>(bias, out);
}

// round 11
// speedup vs baseline: 1.3646x; 1.1592x over previous
#include <cuda_runtime.h>
#include <cuda_fp16.h>
#include <cstdint>

// ---------------- problem constants ----------------
#define CIN   256
#define KOUT  256
#define HH    56
#define WW    56
#define NPF   2304           // 256*3*3 per output filter
#define PH    58
#define PW    58
#define NIMG  32
#define PIX   (HH*WW)        // 3136
#define MTOT  (NIMG*PIX)     // 100352

// ---------------- GEMM tiling ----------------
#define MT    192            // CTA M tile (ragged tail: last CTA covers 128)
#define NT    64             // CTA N tile
#define KC    32             // K chunk (halfs)
#define NCH   72             // 9 taps * 8 chunks of 32 channels
#define NS    4              // pipeline stages
#define NTHR  192            // 6 warps; 2 CTAs/SM -> 170 regs/thread budget

// smem stage: A(192 rows x 80B) + B(64 rows x 80B); 80B stride -> conflict-free
#define ROWB  80
#define ASTG  (MT*ROWB)      // 15360
#define BSTG  (NT*ROWB)      // 5120
#define STG   (ASTG+BSTG)    // 20480
#define SMDYN (NS*STG)       // 81920

// ---------------- device scratch ----------------
__device__ __half g_b[9 * KOUT * CIN];                   // [rs][k][c], +-1
__device__ float  g_alpha[KOUT];
__device__ __half g_xpad[(size_t)NIMG * PH * PW * CIN];  // [n][hp][wp][c]

// ---------------- ptx helpers (family-portable only) ----------------
__device__ __forceinline__ void cp16(uint32_t dst, const void* src) {
    asm volatile("cp.async.cg.shared.global [%0], [%1], 16;"
                 :: "r"(dst), "l"(__cvta_generic_to_global(src)) : "memory");
}
#define CP_COMMIT()  asm volatile("cp.async.commit_group;" ::: "memory")
#define CP_WAIT(N)   asm volatile("cp.async.wait_group %0;" :: "n"(N) : "memory")

#define LDSM4(R, addr)                                                        \
    asm volatile("ldmatrix.sync.aligned.m8n8.x4.shared.b16 {%0,%1,%2,%3}, [%4];" \
                 : "=r"((R)[0]), "=r"((R)[1]), "=r"((R)[2]), "=r"((R)[3])     \
                 : "r"(addr))

#define MMA16816(D, A, B0, B1)                                                \
    asm volatile("mma.sync.aligned.m16n8k16.row.col.f32.f16.f16.f32 "         \
                 "{%0,%1,%2,%3}, {%4,%5,%6,%7}, {%8,%9}, {%0,%1,%2,%3};"      \
                 : "+f"((D)[0]), "+f"((D)[1]), "+f"((D)[2]), "+f"((D)[3])     \
                 : "r"((A)[0]), "r"((A)[1]), "r"((A)[2]), "r"((A)[3]),        \
                   "r"(B0), "r"(B1))

// ---------------------------------------------------------------------------
// K0: ternarize (float4 + warp shuffle reductions). One block per filter.
// ---------------------------------------------------------------------------
__global__ void ternarize_kernel(const float* __restrict__ w) {
    const int o = blockIdx.x;
    const int tid = threadIdx.x;
    const int lane = tid & 31;
    const int wrp = tid >> 5;
    const float4* wo4 = (const float4*)(w + (size_t)o * NPF);
    __shared__ float red[8];
    __shared__ float s_delta;

    float s = 0.f;
    for (int i = tid; i < NPF / 4; i += 256) {
        float4 v = wo4[i];
        s += fabsf(v.x) + fabsf(v.y) + fabsf(v.z) + fabsf(v.w);
    }
    #pragma unroll
    for (int d = 16; d > 0; d >>= 1) s += __shfl_xor_sync(~0u, s, d);
    if (lane == 0) red[wrp] = s;
    __syncthreads();
    if (tid == 0) {
        float t = 0.f;
        #pragma unroll
        for (int i = 0; i < 8; i++) t += red[i];
        s_delta = (0.7f / (float)NPF) * t;
    }
    __syncthreads();
    const float delta = s_delta;

    float cnt = 0.f, asum = 0.f;
    for (int i = tid; i < NPF / 4; i += 256) {
        float4 v = wo4[i];
        float a;
        a = fabsf(v.x); if (a > delta) { cnt += 1.f; asum += a; }
        a = fabsf(v.y); if (a > delta) { cnt += 1.f; asum += a; }
        a = fabsf(v.z); if (a > delta) { cnt += 1.f; asum += a; }
        a = fabsf(v.w); if (a > delta) { cnt += 1.f; asum += a; }
    }
    #pragma unroll
    for (int d = 16; d > 0; d >>= 1) {
        cnt  += __shfl_xor_sync(~0u, cnt, d);
        asum += __shfl_xor_sync(~0u, asum, d);
    }
    if (lane == 0) red[wrp] = cnt;
    __syncthreads();
    float cnt_tot = 0.f;
    if (tid == 0) {
        #pragma unroll
        for (int i = 0; i < 8; i++) cnt_tot += red[i];
        red[0] = cnt_tot;
    }
    __syncthreads();
    cnt_tot = red[0];
    __syncthreads();
    if (lane == 0) red[wrp] = asum;
    __syncthreads();
    if (tid == 0) {
        float t = 0.f;
        #pragma unroll
        for (int i = 0; i < 8; i++) t += red[i];
        g_alpha[o] = t / cnt_tot;
    }

    const float* wo = w + (size_t)o * NPF;
    for (int i = tid; i < NPF; i += 256) {
        float v = wo[i];
        float t = (v > delta) ? 1.f : ((v < -delta) ? -1.f : 0.f);
        int c = i / 9, rs = i % 9;
        g_b[((size_t)rs * KOUT + o) * CIN + c] = __float2half_rn(t);
    }
}

// ---------------------------------------------------------------------------
// K1: pad + NCHW->NHWC transpose + fp16 convert (border rows write zeros).
// ---------------------------------------------------------------------------
__global__ void pad_transpose_kernel(const float* __restrict__ x) {
    __shared__ float s[64][57];
    const int hp = blockIdx.x, c0 = blockIdx.y * 64, n = blockIdx.z;
    __half* dst = g_xpad + ((size_t)(n * PH + hp) * PW) * CIN + c0;

    if (hp == 0 || hp == PH - 1) {
        for (int idx = threadIdx.x; idx < PW * 8; idx += 256) {
            int wp = idx >> 3, u = idx & 7;
            ((uint4*)(dst + (size_t)wp * CIN))[u] = make_uint4(0u, 0u, 0u, 0u);
        }
        return;
    }

    const int h = hp - 1;
    const float* xp = x + ((size_t)(n * CIN + c0) * HH + h) * WW;
    for (int idx = threadIdx.x; idx < 64 * WW; idx += 256) {
        int ci = idx / WW, w = idx - ci * WW;
        s[ci][w] = xp[(size_t)ci * PIX + w];
    }
    __syncthreads();

    for (int idx = threadIdx.x; idx < PW * 64; idx += 256) {
        int wp = idx / 64, ci = idx - wp * 64;
        float v = (wp >= 1 && wp <= WW) ? s[ci][wp - 1] : 0.f;
        dst[(size_t)wp * CIN + ci] = __float2half_rn(v);
    }
}

// ---------------------------------------------------------------------------
// K2: implicit-GEMM conv via mma.sync m16n8k16 (fp32 acc).
// Grid (523, 4): CTA = 192 pixels x 64 out channels. 6 warps (3m x 2n),
// warp tile 64x32, 192 threads -> 170 regs/thread @ 2 CTAs/SM: fragment
// registers for kk=0/kk=1 no longer alias, so LDSM overlaps MMA.
// ---------------------------------------------------------------------------
__global__ void __launch_bounds__(NTHR, 2)
conv_mma_kernel(const float* __restrict__ bias_g, float* __restrict__ out) {
    extern __shared__ __align__(128) char smem[];
    const uint32_t sbase = (uint32_t)__cvta_generic_to_shared(smem);

    const int tid = threadIdx.x;
    const int lane = tid & 31;
    const int wid = tid >> 5;           // 0..5
    const int warp_m = wid >> 1;        // 0..2
    const int warp_n = wid & 1;         // 0..1

    const int p0 = blockIdx.x * MT;
    const int n0 = blockIdx.y * NT;

    __shared__ float s_alpha[NT], s_bias[NT];
    if (tid < NT) { s_alpha[tid] = g_alpha[n0 + tid]; s_bias[tid] = bias_g[n0 + tid]; }

    // ---- per-thread cp.async source/dest precompute ----
    // A: 192 rows x 4 segs = 768 slots / 192 thr = 4 each
    const __half* a_g[4];
    uint32_t sa_off[4];
    #pragma unroll
    for (int q = 0; q < 4; q++) {
        int slot = tid + NTHR * q;
        int row = slot >> 2, seg = slot & 3;
        int p = p0 + row; if (p >= MTOT) p = MTOT - 1;   // clamp (ragged tail)
        int n = p / PIX; int rem = p - n * PIX;
        int h = rem / WW; int w = rem - h * WW;
        a_g[q] = g_xpad + ((size_t)((n * PH + h) * PW + w)) * CIN + seg * 8;
        sa_off[q] = (uint32_t)(row * ROWB + seg * 16);
    }
    // B: 64 rows x 4 segs = 256 slots: q=0 all 192 thr, q=1 only tid<64
    const __half* b_g[2];
    uint32_t sb_off[2];
    #pragma unroll
    for (int q = 0; q < 2; q++) {
        int slot = tid + NTHR * q; if (slot >= 256) slot = 0;
        int row = slot >> 2, seg = slot & 3;
        b_g[q] = g_b + (size_t)(n0 + row) * CIN + seg * 8;
        sb_off[q] = (uint32_t)(row * ROWB + seg * 16);
    }
    const bool bq1 = (tid < 64);

    // ---- ldmatrix address precompute ----
    uint32_t a_lm[4];
    {
        int rr = lane & 15;
        int ch = (lane >> 4) * 8;
        #pragma unroll
        for (int i = 0; i < 4; i++)
            a_lm[i] = (uint32_t)((warp_m * 64 + i * 16 + rr) * ROWB + ch * 2);
    }
    uint32_t b_lm[2];
    {
        int nn = (lane & 7) + ((lane & 16) >> 1);
        int kk0 = lane & 8;
        #pragma unroll
        for (int j = 0; j < 2; j++)
            b_lm[j] = (uint32_t)((warp_n * 32 + j * 16 + nn) * ROWB + kk0 * 2);
    }

    float acc[4][4][4];
    #pragma unroll
    for (int i = 0; i < 4; i++)
        #pragma unroll
        for (int j = 0; j < 4; j++)
            #pragma unroll
            for (int r = 0; r < 4; r++) acc[i][j][r] = 0.f;

    auto fill = [&](int st, int ch) {
        int rs = ch >> 3, cc = ch & 7;
        int r = rs / 3, s = rs - r * 3;
        size_t aoff = (size_t)((r * PW + s) * CIN + cc * KC);
        size_t boff = (size_t)rs * (KOUT * CIN) + cc * KC;
        uint32_t ab = sbase + st * STG;
        uint32_t bb = ab + ASTG;
        #pragma unroll
        for (int q = 0; q < 4; q++) cp16(ab + sa_off[q], a_g[q] + aoff);
        cp16(bb + sb_off[0], b_g[0] + boff);
        if (bq1) cp16(bb + sb_off[1], b_g[1] + boff);
        CP_COMMIT();
    };

    // ---- pipelined mainloop: 3 stages in flight ----
    fill(0, 0); fill(1, 1); fill(2, 2);

    int st = 0;
    #pragma unroll 1
    for (int ch = 0; ch < NCH; ch++) {
        CP_WAIT(2);
        __syncthreads();
        if (ch + 3 < NCH) fill((st + 3) & (NS - 1), ch + 3);
        else              CP_COMMIT();

        uint32_t ab = sbase + st * STG;
        uint32_t bb = ab + ASTG;
        // distinct fragment arrays per kk -> no register aliasing at 170 regs
        uint32_t a[2][4][4], b[2][2][4];
        #pragma unroll
        for (int kk = 0; kk < 2; kk++) {
            #pragma unroll
            for (int i = 0; i < 4; i++) LDSM4(a[kk][i], ab + a_lm[i] + kk * 32);
            #pragma unroll
            for (int j = 0; j < 2; j++) LDSM4(b[kk][j], bb + b_lm[j] + kk * 32);
            #pragma unroll
            for (int i = 0; i < 4; i++)
                #pragma unroll
                for (int j2 = 0; j2 < 4; j2++)
                    MMA16816(acc[i][j2], a[kk][i],
                             b[kk][j2 >> 1][(j2 & 1) * 2],
                             b[kk][j2 >> 1][(j2 & 1) * 2 + 1]);
        }
        st = (st + 1) & (NS - 1);
    }
    __syncthreads();

    // ---- epilogue: stage through smem, out = alpha*acc + bias ----
    float* stile = (float*)smem;   // [192][65] = 49.9KB, fits in 80KB dyn smem
    #pragma unroll
    for (int i = 0; i < 4; i++)
        #pragma unroll
        for (int j2 = 0; j2 < 4; j2++) {
            int no = warp_n * 32 + j2 * 8 + (lane & 3) * 2;
            int m0 = warp_m * 64 + i * 16 + (lane >> 2);
            stile[m0 * 65 + no]           = acc[i][j2][0];
            stile[m0 * 65 + no + 1]       = acc[i][j2][1];
            stile[(m0 + 8) * 65 + no]     = acc[i][j2][2];
            stile[(m0 + 8) * 65 + no + 1] = acc[i][j2][3];
        }
    __syncthreads();

    int p = p0 + tid;
    if (p < MTOT) {
        int nimg = p / PIX; int hw = p - nimg * PIX;
        float* ob = out + ((size_t)nimg * KOUT + n0) * PIX + hw;
        #pragma unroll
        for (int k = 0; k < NT; k++) {
            float v = stile[tid * 65 + k];
            ob[(size_t)k * PIX] = fmaf(s_alpha[k], v, s_bias[k]);
        }
    }
}

// ---------------------------------------------------------------------------
extern "C" void kernel_launch(void* const* d_in, const int* in_sizes, int n_in,
                              void* d_out, int out_size) {
    const float* x      = (const float*)d_in[0];
    const float* weight = (const float*)d_in[1];
    const float* bias   = (const float*)d_in[2];
    float* out          = (float*)d_out;

    cudaFuncSetAttribute(conv_mma_kernel,
                         cudaFuncAttributeMaxDynamicSharedMemorySize, SMDYN);

    ternarize_kernel<<<KOUT, 256>>>(weight);
    pad_transpose_kernel<<<dim3(PH, 4, NIMG), 256>>>(x);
    const int mtiles = (MTOT + MT - 1) / MT;   // 523
    conv_mma_kernel<<<dim3(mtiles, KOUT / NT), NTHR, SMDYN>>>(bias, out);
}